// round 3
// baseline (speedup 1.0000x reference)
#include <cuda_runtime.h>

// gconv_19301583028599 — adaptive graph conv as fused flash-attention.
//
// y = softmax(relu(adj @ adj^T)) @ X      (X = x transposed to [N, B*INP])
// out[b,n,o] = x[b,n,:]·W0[n,:,o] + y[b,n,:]·W1[n,:,o] + bias[n,o]
// W_k[n,i,o] = adj[n,:]·wp[:,k,i,o],  bias[n,o] = adj[n,:]·bp[:,o]

#define NN   8192
#define BB   32
#define EMB  16
#define HID  64
#define TQ   64
#define TK   64

// scratch: Xt[m][b*2+c] = x[b][m][c]   (2 MB)
__device__ float g_Xt[NN * 64];

__global__ void transpose_x_kernel(const float* __restrict__ x) {
    int m = blockIdx.x * blockDim.x + threadIdx.x;
    if (m >= NN) return;
    float row[64];
#pragma unroll
    for (int b = 0; b < BB; b++) {
        float2 v = *(const float2*)(x + ((size_t)b * NN + m) * 2);
        row[2 * b]     = v.x;
        row[2 * b + 1] = v.y;
    }
    float4* dst = (float4*)(g_Xt + (size_t)m * 64);
#pragma unroll
    for (int q = 0; q < 16; q++) dst[q] = ((float4*)row)[q];
}

struct __align__(16) Smem {
    float Qs[TQ][EMB + 1];     // adj rows of this block (padded: rows +4 -> bank +4)
    float Ps[TQ][68];          // P tile during mainloop; y tile in epilogue
    union {
        struct { float Kt[EMB][TK]; float Vs[TK][64]; } mm;   // 4KB + 16KB
        struct { float wps[EMB * 4 * 64]; float bps[EMB * 64]; } ep; // 16KB + 4KB
    } u;
};

__global__ __launch_bounds__(256, 1) void gconv_attn_kernel(
    const float* __restrict__ adj,
    const float* __restrict__ wp,
    const float* __restrict__ bp,
    float* __restrict__ out)
{
    __shared__ Smem sm;
    const int tid = threadIdx.x;
    const int i = tid >> 4;    // row group 0..15 (4 q-rows each)
    const int j = tid & 15;    // col group 0..15 (4 v-cols each)
    const int n0 = blockIdx.x * TQ;

    // load Q tile = adj rows n0..n0+63 (scalar: padded rows)
    for (int t = tid; t < TQ * EMB; t += 256) {
        int r = t >> 4, d = t & 15;
        sm.Qs[r][d] = adj[(n0 + r) * EMB + d];
    }

    float acc[4][4];
    float l[4];
#pragma unroll
    for (int a = 0; a < 4; a++) {
        l[a] = 0.f;
#pragma unroll
        for (int b = 0; b < 4; b++) acc[a][b] = 0.f;
    }

    for (int kt = 0; kt < NN; kt += TK) {
        __syncthreads();   // prev PV done (Vs/Ps safe to overwrite); covers Qs on iter 0

        // K tile transposed: Kt[d][r] = adj[kt+r][d]
        for (int t = tid; t < TK * EMB; t += 256) {
            int r = t >> 4, d = t & 15;
            sm.u.mm.Kt[d][r] = adj[(kt + r) * EMB + d];
        }
        // V tile: Vs[r][c] = Xt[kt+r][c]
        {
            const float4* src = (const float4*)(g_Xt + (size_t)kt * 64);
            float4* dst = (float4*)&sm.u.mm.Vs[0][0];
#pragma unroll
            for (int t = 0; t < 4; t++) dst[tid + 256 * t] = src[tid + 256 * t];
        }
        __syncthreads();

        // ---- scores: s[rr][cc] = q_{i*4+rr} . k_{j*4+cc} ----
        float s[4][4];
#pragma unroll
        for (int a = 0; a < 4; a++)
#pragma unroll
            for (int b = 0; b < 4; b++) s[a][b] = 0.f;
#pragma unroll
        for (int d = 0; d < EMB; d++) {
            float4 kv = ((const float4*)&sm.u.mm.Kt[d][0])[j];
#pragma unroll
            for (int rr = 0; rr < 4; rr++) {
                float q = sm.Qs[i * 4 + rr][d];
                s[rr][0] += q * kv.x;
                s[rr][1] += q * kv.y;
                s[rr][2] += q * kv.z;
                s[rr][3] += q * kv.w;
            }
        }
        // p = exp(relu(s))  (no max-subtraction needed: s in [0, ~25]; clamp for safety)
#pragma unroll
        for (int rr = 0; rr < 4; rr++) {
            float4 pv;
            pv.x = __expf(fminf(fmaxf(s[rr][0], 0.f), 80.f));
            pv.y = __expf(fminf(fmaxf(s[rr][1], 0.f), 80.f));
            pv.z = __expf(fminf(fmaxf(s[rr][2], 0.f), 80.f));
            pv.w = __expf(fminf(fmaxf(s[rr][3], 0.f), 80.f));
            ((float4*)&sm.Ps[i * 4 + rr][0])[j] = pv;
        }
        __syncthreads();

        // ---- PV accumulate + row-sums (redundant per j-group: avoids comm) ----
#pragma unroll 8
        for (int kk = 0; kk < TK; kk++) {
            float4 v = ((const float4*)&sm.u.mm.Vs[kk][0])[j];
#pragma unroll
            for (int rr = 0; rr < 4; rr++) {
                float p = sm.Ps[i * 4 + rr][kk];
                l[rr] += p;
                acc[rr][0] += p * v.x;
                acc[rr][1] += p * v.y;
                acc[rr][2] += p * v.z;
                acc[rr][3] += p * v.w;
            }
        }
    }
    __syncthreads();   // all PV reads of Ps done before overwriting with y

    // normalized y -> Ps (reused as y tile)
#pragma unroll
    for (int rr = 0; rr < 4; rr++) {
        float inv = 1.f / l[rr];
        float4 yv = make_float4(acc[rr][0] * inv, acc[rr][1] * inv,
                                acc[rr][2] * inv, acc[rr][3] * inv);
        ((float4*)&sm.Ps[i * 4 + rr][0])[j] = yv;
    }

    // pools into smem (union region: Kt/Vs dead now)
    for (int t = tid; t < (EMB * 4 * 64) / 4; t += 256)
        ((float4*)sm.u.ep.wps)[t] = ((const float4*)wp)[t];
    ((float4*)sm.u.ep.bps)[tid] = ((const float4*)bp)[tid];
    __syncthreads();

    // ---- epilogue: out[b,n,o] = bias + x·W0 + y·W1 ----
    const int o  = tid & 63;
    const int ng = tid >> 6;       // 0..3
    for (int ii = 0; ii < 16; ii++) {
        int n = ng * 16 + ii;      // local row 0..63
        float w00 = 0.f, w01 = 0.f, w10 = 0.f, w11 = 0.f, bbv = 0.f;
#pragma unroll
        for (int d = 0; d < EMB; d++) {
            float a = sm.Qs[n][d];
            // wp[d][k][i][o] at ((d*4 + k*2 + i)*64 + o)
            w00 += a * sm.u.ep.wps[(d * 4 + 0) * 64 + o];
            w01 += a * sm.u.ep.wps[(d * 4 + 1) * 64 + o];
            w10 += a * sm.u.ep.wps[(d * 4 + 2) * 64 + o];
            w11 += a * sm.u.ep.wps[(d * 4 + 3) * 64 + o];
            bbv += a * sm.u.ep.bps[d * 64 + o];
        }
        int gn = n0 + n;
        const float* xrow = g_Xt + (size_t)gn * 64;   // Xt[gn][2b+c] = x[b][gn][c]
        float* orow = out + (size_t)gn * 64 + o;
#pragma unroll 4
        for (int b = 0; b < BB; b++) {
            float2 xv = *(const float2*)(xrow + 2 * b);
            float2 yv = *(const float2*)(&sm.Ps[n][2 * b]);
            float r = bbv + xv.x * w00 + xv.y * w01 + yv.x * w10 + yv.y * w11;
            orow[(size_t)b * (NN * 64)] = r;
        }
    }
}

extern "C" void kernel_launch(void* const* d_in, const int* in_sizes, int n_in,
                              void* d_out, int out_size) {
    const float* x   = (const float*)d_in[0];   // [32, 8192, 2]
    const float* adj = (const float*)d_in[1];   // [8192, 16]
    const float* wp  = (const float*)d_in[2];   // [16, 2, 2, 64]
    const float* bp  = (const float*)d_in[3];   // [16, 64]
    float* out = (float*)d_out;                 // [32, 8192, 64]

    transpose_x_kernel<<<NN / 256, 256>>>(x);
    gconv_attn_kernel<<<NN / TQ, 256>>>(adj, wp, bp, out);
}